// round 2
// baseline (speedup 1.0000x reference)
#include <cuda_runtime.h>
#include <cuda_bf16.h>

// CGA motor sandwich: out = grade1( M * P * rev(M) )[:, :6]
// Exploits: motor has 127 nonzero comps, point has 8; only 6 outputs needed.
// Stage 1: mx[res] += sgn * m[a] * p[b]        (127*8 = 1016 pairs, smem scatter)
// Stage 2: out[k]  += sgn' * mx[a] * m[b]       (6*127 = 762 pairs, a = res[mm[b]*256+pm[k]])
//          with sgn' = sgn[a*256+mm[b]] * motor_reverse_sign[b] folded in.
// One warp per batch element; packed pair tables rebuilt per block from the
// (L2-resident, shared) global tables.

#define NB 256
#define NM 127   // motor components
#define NP 8     // point components
#define NOUT 6
#define S1N (NM * NP)     // 1016
#define S2N (NOUT * NM)   // 762
#define WARPS 8

__global__ __launch_bounds__(256, 1)
void cga_sandwich_kernel(const float* __restrict__ motor,
                         const float* __restrict__ x,
                         const int* __restrict__ res_tab,
                         const int* __restrict__ sgn_tab,
                         const int* __restrict__ pm_g,
                         const int* __restrict__ mm_g,
                         const int* __restrict__ mrs_g,
                         float* __restrict__ out,
                         int Bn)
{
    __shared__ int mm[NM];
    __shared__ int mrs[NM];
    __shared__ int pm[NP];
    __shared__ int s1[S1N];
    __shared__ int s2[S2N];
    __shared__ float sm[WARPS][NM];   // compact motor per warp
    __shared__ float sp[WARPS][NP];   // point per warp
    __shared__ float smx[WARPS][NB];  // intermediate mx per warp

    const int tid = threadIdx.x;

    // ---- load index masks ----
    for (int i = tid; i < NM; i += 256) { mm[i] = mm_g[i]; mrs[i] = mrs_g[i]; }
    if (tid < NP) pm[tid] = pm_g[tid];
    __syncthreads();

    // ---- build packed stage-1 table: res(8b) | a(7b)<<8 | b(3b)<<15 | neg<<18 ----
    for (int t = tid; t < S1N; t += 256) {
        int a = t >> 3;          // 0..126 compact motor index
        int b = t & 7;           // 0..7   compact point index
        int idx = mm[a] * NB + pm[b];
        int r = res_tab[idx];
        int neg = (sgn_tab[idx] < 0) ? 1 : 0;
        s1[t] = r | (a << 8) | (b << 15) | (neg << 18);
    }

    // ---- build packed stage-2 table: a_pos(8b) | neg<<8 ----
    // For target blade r=pm[k] and motor comp j=mm[b], the unique left operand
    // is a = pos[mask_j ^ mask_r] = res_tab[mm[b]*256 + pm[k]].
    for (int t = tid; t < S2N; t += 256) {
        int k = t / NM;
        int b = t - k * NM;
        int apos = res_tab[mm[b] * NB + pm[k]];
        int s = sgn_tab[apos * NB + mm[b]] * mrs[b];   // fold reverse sign
        s2[t] = apos | (((s < 0) ? 1 : 0) << 8);
    }
    __syncthreads();

    // ---- per-warp batch processing ----
    const int w = tid >> 5;
    const int lane = tid & 31;
    const int batch = blockIdx.x * WARPS + w;
    if (batch >= Bn) return;

    // load compact motor, zero mx
    const float* mrow = motor + (size_t)batch * NM;
    for (int i = lane; i < NM; i += 32) sm[w][i] = mrow[i];
    for (int i = lane; i < NB; i += 32) smx[w][i] = 0.0f;

    // build point: [x0..x5, h-0.5, h+0.5], h = 0.5*|x|^2
    if (lane == 0) {
        const float* xr = x + (size_t)batch * NOUT;
        float h = 0.0f;
        #pragma unroll
        for (int i = 0; i < NOUT; i++) {
            float v = xr[i];
            sp[w][i] = v;
            h += v * v;
        }
        h *= 0.5f;
        sp[w][6] = h - 0.5f;
        sp[w][7] = h + 0.5f;
    }
    __syncwarp();

    // ---- stage 1: mx = M * P (scatter into smem) ----
    for (int e = lane; e < S1N; e += 32) {
        int ent = s1[e];
        int r = ent & 255;
        int a = (ent >> 8) & 127;
        int b = (ent >> 15) & 7;
        float v = sm[w][a] * sp[w][b];
        if (ent & (1 << 18)) v = -v;
        atomicAdd(&smx[w][r], v);
    }
    __syncwarp();

    // ---- stage 2: out[k] = sum_b sgn' * mx[a(b,k)] * m[b] ----
    #pragma unroll
    for (int k = 0; k < NOUT; k++) {
        float acc = 0.0f;
        const int base = k * NM;
        for (int b = lane; b < NM; b += 32) {
            int ent = s2[base + b];
            float v = smx[w][ent & 255] * sm[w][b];
            acc += (ent & 256) ? -v : v;
        }
        #pragma unroll
        for (int off = 16; off; off >>= 1)
            acc += __shfl_xor_sync(0xffffffffu, acc, off);
        if (lane == 0) out[(size_t)batch * NOUT + k] = acc;
    }
}

extern "C" void kernel_launch(void* const* d_in, const int* in_sizes, int n_in,
                              void* d_out, int out_size)
{
    const float* motor = (const float*)d_in[0];   // [B, 127]
    const float* x     = (const float*)d_in[1];   // [B, 6]
    // d_in[2] = left_idx, d_in[3] = right_idx (unused: table is a dense grid)
    const int* res_tab = (const int*)d_in[4];     // [65536]
    const int* sgn_tab = (const int*)d_in[5];     // [65536]
    const int* pm      = (const int*)d_in[6];     // [8]
    const int* mm      = (const int*)d_in[7];     // [127]
    const int* mrs     = (const int*)d_in[8];     // [127]
    float* out = (float*)d_out;

    int Bn = in_sizes[0] / NM;   // 1024
    int grid = (Bn + WARPS - 1) / WARPS;
    cga_sandwich_kernel<<<grid, 256>>>(motor, x, res_tab, sgn_tab,
                                       pm, mm, mrs, out, Bn);
}

// round 4
// speedup vs baseline: 1.8853x; 1.8853x over previous
#include <cuda_runtime.h>
#include <cuda_bf16.h>

// CGA motor sandwich out = grade1(M * P * ~M)[:, :6], Cl(7,1), B=1024.
// All combinatorial tables (blade ordering, product signs, pair lists) are
// evaluated at COMPILE TIME via constexpr — the algebra is fixed (n=6, d=8).
//
// Stage 1 (gather form): mx lives only on the 128 odd-grade blades.
//   mx[bin] = sum_{b=0..7} sign * m[a(bin,b)] * p[b],  a = mask(bin)^ (1<<b)
//   8 entries per bin (invalid -> points at sm[127]==0, branch-free).
// Stage 2: out[k] = sum_{b=0..126} sign' * mx[bin(k,b)] * m[b]
//   with motor-reverse sign folded in at compile time.
//
// One warp per batch element, warp-autonomous (no block barriers, no atomics).

#define NM 127

struct Tables {
    int bin[128 * 8];   // a(7b) | b(3b)<<7 | neg<<10
    int s2[6 * 128];    // bin(7b) | neg<<7   (b=127 pad -> *sm[127]==0)
};

__host__ __device__ constexpr int popc8(int m) {
    int c = 0;
    for (int i = 0; i < 8; i++) c += (m >> i) & 1;
    return c;
}

__host__ __device__ constexpr int sign_of(int a, int b) {
    int s = 1;
    int aa = a >> 1;
    while (aa) { if (popc8(aa & b) & 1) s = -s; aa >>= 1; }
    if ((a & b) & 0x80) s = -s;   // metric: only basis vector 7 squares to -1
    return s;
}

__host__ __device__ constexpr Tables make_tables() {
    Tables T{};
    // masks sorted by (popcount, value) — reference ordering
    int masks[256] = {};
    int t = 0;
    for (int g = 0; g <= 8; ++g)
        for (int m = 0; m < 256; ++m)
            if (popc8(m) == g) masks[t++] = m;

    int mmmask[127] = {};  int mmrank[256] = {};  int nm = 0;
    int oddmask[128] = {}; int binrank[256] = {}; int nodd = 0;
    for (int i = 0; i < 256; ++i) {
        int m = masks[i], g = popc8(m);
        if ((g & 1) == 0 && m != 255) { mmmask[nm] = m; mmrank[m] = nm; ++nm; }
        if (g & 1)                    { oddmask[nodd] = m; binrank[m] = nodd; ++nodd; }
    }

    // stage-1 bins: for odd blade rm, contributions (a, b) with mask_a = rm ^ (1<<b)
    for (int bi = 0; bi < 128; ++bi) {
        int rm = oddmask[bi];
        for (int b = 0; b < 8; ++b) {
            int pmask = 1 << b;
            int am = rm ^ pmask;
            int ent = 0;
            if (am == 255) {
                ent = 127;                         // pseudoscalar not in motor -> zero slot
            } else {
                int a = mmrank[am];
                int s = sign_of(am, pmask);
                ent = a | (b << 7) | ((s < 0 ? 1 : 0) << 10);
            }
            T.bin[bi * 8 + b] = ent;
        }
    }

    // stage 2: out blade mask 1<<k, motor comp j -> left operand bin(mask (1<<k)^mm[j])
    for (int k = 0; k < 6; ++k) {
        for (int b = 0; b < 128; ++b) {
            int ent = 0;
            if (b == 127) {
                ent = 0;                           // pad: multiplies sm[127]==0
            } else {
                int jm = mmmask[b];
                int im = (1 << k) ^ jm;
                int bi = binrank[im];
                int g  = popc8(jm);
                int rs = ((g * (g - 1) / 2) & 1) ? -1 : 1;   // reverse sign
                int s  = sign_of(im, jm) * rs;
                ent = bi | ((s < 0 ? 1 : 0) << 7);
            }
            T.s2[k * 128 + b] = ent;
        }
    }
    return T;
}

__device__ const Tables g_T = make_tables();

__global__ void cga_sandwich_kernel(const float* __restrict__ motor,
                                    const float* __restrict__ x,
                                    float* __restrict__ out,
                                    int Bn)
{
    __shared__ float s_m[4][128];
    __shared__ float s_mx[4][128];

    const int w    = threadIdx.x >> 5;
    const int lane = threadIdx.x & 31;
    const int batch = blockIdx.x * 4 + w;
    if (batch >= Bn) return;   // warp-uniform

    float* sm  = s_m[w];
    float* smx = s_mx[w];

    // load compact motor (pad slot 127 = 0: used by invalid/pad table entries)
    const float* mrow = motor + (size_t)batch * NM;
    #pragma unroll
    for (int i = 0; i < 4; i++) {
        int idx = lane + 32 * i;
        sm[idx] = (idx < NM) ? mrow[idx] : 0.0f;
    }

    // point in lanes 0..7: [x0..x5, h-0.5, h+0.5], h = 0.5*|x|^2
    float pv = 0.0f;
    if (lane < 6) pv = x[(size_t)batch * 6 + lane];
    float sq = pv * pv;
    #pragma unroll
    for (int o = 4; o; o >>= 1) sq += __shfl_xor_sync(0xffffffffu, sq, o);
    float h = 0.5f * sq;
    if (lane == 6) pv = h - 0.5f;
    else if (lane == 7) pv = h + 0.5f;
    __syncwarp();

    // ---- stage 1: gather mx bins (no atomics) ----
    #pragma unroll
    for (int q = 0; q < 4; q++) {
        const int bin = q * 32 + lane;
        float acc = 0.0f;
        #pragma unroll
        for (int e = 0; e < 8; e++) {
            int ent  = __ldg(&g_T.bin[bin * 8 + e]);
            float p  = __shfl_sync(0xffffffffu, pv, (ent >> 7) & 7);
            float mv = sm[ent & 127];
            acc = fmaf((ent & 1024) ? -mv : mv, p, acc);
        }
        smx[bin] = acc;
    }
    __syncwarp();

    // ---- stage 2: six outputs, 127 terms each ----
    float o0 = 0.f, o1 = 0.f, o2 = 0.f, o3 = 0.f, o4 = 0.f, o5 = 0.f;
    #pragma unroll
    for (int i = 0; i < 4; i++) {
        const int b = i * 32 + lane;
        const float mv = sm[b];
        {
            int e = __ldg(&g_T.s2[0 * 128 + b]);
            float v = smx[e & 127] * mv;
            o0 += (e & 128) ? -v : v;
        }
        {
            int e = __ldg(&g_T.s2[1 * 128 + b]);
            float v = smx[e & 127] * mv;
            o1 += (e & 128) ? -v : v;
        }
        {
            int e = __ldg(&g_T.s2[2 * 128 + b]);
            float v = smx[e & 127] * mv;
            o2 += (e & 128) ? -v : v;
        }
        {
            int e = __ldg(&g_T.s2[3 * 128 + b]);
            float v = smx[e & 127] * mv;
            o3 += (e & 128) ? -v : v;
        }
        {
            int e = __ldg(&g_T.s2[4 * 128 + b]);
            float v = smx[e & 127] * mv;
            o4 += (e & 128) ? -v : v;
        }
        {
            int e = __ldg(&g_T.s2[5 * 128 + b]);
            float v = smx[e & 127] * mv;
            o5 += (e & 128) ? -v : v;
        }
    }

    #pragma unroll
    for (int off = 16; off; off >>= 1) {
        o0 += __shfl_xor_sync(0xffffffffu, o0, off);
        o1 += __shfl_xor_sync(0xffffffffu, o1, off);
        o2 += __shfl_xor_sync(0xffffffffu, o2, off);
        o3 += __shfl_xor_sync(0xffffffffu, o3, off);
        o4 += __shfl_xor_sync(0xffffffffu, o4, off);
        o5 += __shfl_xor_sync(0xffffffffu, o5, off);
    }

    if (lane == 0) {
        float2* op = (float2*)(out + (size_t)batch * 6);   // 8B aligned (24B stride)
        op[0] = make_float2(o0, o1);
        op[1] = make_float2(o2, o3);
        op[2] = make_float2(o4, o5);
    }
}

extern "C" void kernel_launch(void* const* d_in, const int* in_sizes, int n_in,
                              void* d_out, int out_size)
{
    const float* motor = (const float*)d_in[0];   // [B, 127]
    const float* x     = (const float*)d_in[1];   // [B, 6]
    float* out = (float*)d_out;

    int Bn = in_sizes[0] / NM;                    // 1024
    int grid = (Bn + 3) / 4;                      // 4 warps/block, 1 batch/warp
    cga_sandwich_kernel<<<grid, 128>>>(motor, x, out, Bn);
}

// round 5
// speedup vs baseline: 2.4579x; 1.3037x over previous
#include <cuda_runtime.h>
#include <cuda_bf16.h>

// CGA motor sandwich out = grade1(M * P * ~M)[:, :6], Cl(7,1), B=1024.
// Compile-time tables; ONE 128-thread block per batch element:
//   - coalesced 1-LDG motor load into smem (pad slot 127 = 0)
//   - stage 1: one odd-grade bin per thread, 8 table entries via 2x LDG.128
//   - stage 2: 6 outputs; thread b handles term b of each output (2x LDG.128
//     packed table), warp shfl-reduce + 4-warp smem combine.

#define NM 127

struct Tables {
    int bin[128 * 8];   // a(7b) | b(3b)<<7 | neg<<10
    int s2[128 * 8];    // [b][k] packed: bin(7b) | neg<<7 ; k=6,7 pad unused
};

__host__ __device__ constexpr int popc8(int m) {
    int c = 0;
    for (int i = 0; i < 8; i++) c += (m >> i) & 1;
    return c;
}

__host__ __device__ constexpr int sign_of(int a, int b) {
    int s = 1;
    int aa = a >> 1;
    while (aa) { if (popc8(aa & b) & 1) s = -s; aa >>= 1; }
    if ((a & b) & 0x80) s = -s;   // metric: only basis vector 7 squares to -1
    return s;
}

__host__ __device__ constexpr Tables make_tables() {
    Tables T{};
    // masks sorted by (popcount, value) — reference ordering
    int masks[256] = {};
    int t = 0;
    for (int g = 0; g <= 8; ++g)
        for (int m = 0; m < 256; ++m)
            if (popc8(m) == g) masks[t++] = m;

    int mmmask[127] = {};  int mmrank[256] = {};  int nm = 0;
    int oddmask[128] = {}; int binrank[256] = {}; int nodd = 0;
    for (int i = 0; i < 256; ++i) {
        int m = masks[i], g = popc8(m);
        if ((g & 1) == 0 && m != 255) { mmmask[nm] = m; mmrank[m] = nm; ++nm; }
        if (g & 1)                    { oddmask[nodd] = m; binrank[m] = nodd; ++nodd; }
    }

    // stage-1 bins: for odd blade rm, contributions (a, b) with mask_a = rm ^ (1<<b)
    for (int bi = 0; bi < 128; ++bi) {
        int rm = oddmask[bi];
        for (int b = 0; b < 8; ++b) {
            int pmask = 1 << b;
            int am = rm ^ pmask;
            int ent = 0;
            if (am == 255) {
                ent = 127;                 // pseudoscalar not in motor -> sm[127]==0
            } else {
                int a = mmrank[am];
                int s = sign_of(am, pmask);
                ent = a | (b << 7) | ((s < 0 ? 1 : 0) << 10);
            }
            T.bin[bi * 8 + b] = ent;
        }
    }

    // stage 2 packed [b][k]: out blade 1<<k, motor comp j=mm[b]
    for (int b = 0; b < 128; ++b) {
        for (int k = 0; k < 8; ++k) {
            int ent = 0;
            if (b < NM && k < 6) {
                int jm = mmmask[b];
                int im = (1 << k) ^ jm;
                int bi = binrank[im];
                int g  = popc8(jm);
                int rs = ((g * (g - 1) / 2) & 1) ? -1 : 1;   // reverse sign
                int s  = sign_of(im, jm) * rs;
                ent = bi | ((s < 0 ? 1 : 0) << 7);
            }
            T.s2[b * 8 + k] = ent;         // pads multiply sm[127]==0 / unused
        }
    }
    return T;
}

__device__ const Tables g_T = make_tables();

__device__ __forceinline__ float s1_term(int ent, const float* sm, const float* sp) {
    float mv = sm[ent & 127];
    float pp = sp[(ent >> 7) & 7];
    return (ent & 1024) ? -mv * pp : mv * pp;
}

__global__ __launch_bounds__(128)
void cga_sandwich_kernel(const float* __restrict__ motor,
                         const float* __restrict__ x,
                         float* __restrict__ out)
{
    __shared__ float sm[128];
    __shared__ float sp[8];
    __shared__ float smx[128];
    __shared__ float red[4][6];

    const int t = threadIdx.x;
    const int batch = blockIdx.x;

    // coalesced motor load; pad slot 127 = 0
    sm[t] = (t < NM) ? motor[(size_t)batch * NM + t] : 0.0f;

    // point [x0..x5, h-0.5, h+0.5] built by threads 0..7 (x LDGs broadcast)
    if (t < 8) {
        const float* xr = x + (size_t)batch * 6;
        float h = 0.0f;
        #pragma unroll
        for (int i = 0; i < 6; i++) { float v = xr[i]; h += v * v; }
        h *= 0.5f;
        float v;
        if (t < 6)       v = xr[t];
        else if (t == 6) v = h - 0.5f;
        else             v = h + 0.5f;
        sp[t] = v;
    }
    __syncthreads();

    // ---- stage 1: one bin per thread, 8 entries via 2x LDG.128 ----
    {
        const int4* bt = (const int4*)(g_T.bin + t * 8);
        int4 e0 = __ldg(bt);
        int4 e1 = __ldg(bt + 1);
        float acc = s1_term(e0.x, sm, sp);
        acc += s1_term(e0.y, sm, sp);
        acc += s1_term(e0.z, sm, sp);
        acc += s1_term(e0.w, sm, sp);
        acc += s1_term(e1.x, sm, sp);
        acc += s1_term(e1.y, sm, sp);
        acc += s1_term(e1.z, sm, sp);
        acc += s1_term(e1.w, sm, sp);
        smx[t] = acc;
    }
    __syncthreads();

    // ---- stage 2: thread t = motor term t for all 6 outputs ----
    float o[6];
    {
        const int4* st = (const int4*)(g_T.s2 + t * 8);
        int4 f0 = __ldg(st);
        int4 f1 = __ldg(st + 1);
        const float mv = sm[t];
        int e[6] = { f0.x, f0.y, f0.z, f0.w, f1.x, f1.y };
        #pragma unroll
        for (int k = 0; k < 6; k++) {
            float v = smx[e[k] & 127] * mv;
            o[k] = (e[k] & 128) ? -v : v;
        }
    }

    // warp reduce (4 warps in parallel)
    #pragma unroll
    for (int off = 16; off; off >>= 1) {
        #pragma unroll
        for (int k = 0; k < 6; k++)
            o[k] += __shfl_xor_sync(0xffffffffu, o[k], off);
    }
    const int w = t >> 5, lane = t & 31;
    if (lane == 0) {
        #pragma unroll
        for (int k = 0; k < 6; k++) red[w][k] = o[k];
    }
    __syncthreads();

    if (t < 6)
        out[(size_t)batch * 6 + t] = red[0][t] + red[1][t] + red[2][t] + red[3][t];
}

extern "C" void kernel_launch(void* const* d_in, const int* in_sizes, int n_in,
                              void* d_out, int out_size)
{
    const float* motor = (const float*)d_in[0];   // [B, 127]
    const float* x     = (const float*)d_in[1];   // [B, 6]
    float* out = (float*)d_out;

    int Bn = in_sizes[0] / NM;                    // 1024
    cga_sandwich_kernel<<<Bn, 128>>>(motor, x, out);
}